// round 1
// baseline (speedup 1.0000x reference)
#include <cuda_runtime.h>
#include <math.h>

#define NN 100000
#define NE 1600000
#define SCAN_B 98   // ceil(NN/1024)

// ---------------- scratch (static device memory; no allocations) ----------------
__device__ int   g_is64;
__device__ int   g_deg[NN];
__device__ int   g_incl[NN];
__device__ int   g_bsum[SCAN_B];
__device__ int   g_boff[SCAN_B];
__device__ int   g_off[NN + 1];
__device__ int   g_cur[NN];
__device__ int   g_srcs[NE];
__device__ float g_h1[NN * 64];
__device__ float g_s1[NN * 8];
__device__ float g_t1[NN * 8];
__device__ float g_z [NN * 64];
__device__ float g_h2[NN * 16];
__device__ float g_s2[NN];
__device__ float g_t2[NN];

// ---------------- edge dtype detection (int64 vs int32) ----------------
// If edge_index is int64 (little endian), every odd 32-bit word of the first
// elements is 0 (values < 100000). If int32, odd words are random node ids.
__global__ void k_detect(const int* __restrict__ w) {
    if (threadIdx.x == 0) {
        int is64 = 1;
        #pragma unroll
        for (int k = 0; k < 8; k++)
            if (w[2 * k + 1] != 0) is64 = 0;
        g_is64 = is64;
    }
}

__global__ void k_zero_deg() {
    int i = blockIdx.x * blockDim.x + threadIdx.x;
    if (i < NN) g_deg[i] = 0;
}

__global__ void k_hist(const int* __restrict__ w) {
    int i = blockIdx.x * blockDim.x + threadIdx.x;
    if (i >= NE) return;
    long long di = g_is64 ? 2LL * (NE + (long long)i) : (long long)(NE + i);
    atomicAdd(&g_deg[w[di]], 1);
}

__global__ void k_scanA() {
    __shared__ int sh[1024];
    int i = blockIdx.x * 1024 + threadIdx.x;
    int v = (i < NN) ? g_deg[i] : 0;
    sh[threadIdx.x] = v;
    __syncthreads();
    #pragma unroll
    for (int ofs = 1; ofs < 1024; ofs <<= 1) {
        int add = (threadIdx.x >= ofs) ? sh[threadIdx.x - ofs] : 0;
        __syncthreads();
        sh[threadIdx.x] += add;
        __syncthreads();
    }
    if (i < NN) g_incl[i] = sh[threadIdx.x];
    if (threadIdx.x == 1023) g_bsum[blockIdx.x] = sh[1023];
}

__global__ void k_scanB() {
    if (threadIdx.x == 0) {
        int run = 0;
        for (int b = 0; b < SCAN_B; b++) { g_boff[b] = run; run += g_bsum[b]; }
        g_off[0] = 0;
    }
}

__global__ void k_scanC() {
    int i = blockIdx.x * blockDim.x + threadIdx.x;
    if (i < NN) {
        g_off[i + 1] = g_incl[i] + g_boff[i >> 10];
        g_cur[i] = 0;
    }
}

__global__ void k_scatter(const int* __restrict__ w) {
    int i = blockIdx.x * blockDim.x + threadIdx.x;
    if (i >= NE) return;
    int is64 = g_is64;
    int s = w[is64 ? 2LL * i : (long long)i];
    int d = w[is64 ? 2LL * (NE + (long long)i) : (long long)(NE + i)];
    int pos = g_off[d] + atomicAdd(&g_cur[d], 1);
    g_srcs[pos] = s;
}

// ---------------- GEMM1: h1 = x @ W1 (+ s1/t1 epilogue), packed f32x2 FFMA ----------------
// Block: 128 threads, tile 128 rows x 64 cols, K-tiles of 32.
// Thread (tr = t>>3, tc = t&7): rows tr+16r (r=0..7), cols tc*8..tc*8+7 (one head).
__global__ __launch_bounds__(128, 4) void k_gemm1(
    const float* __restrict__ x, const float* __restrict__ W1,
    const float* __restrict__ a1s, const float* __restrict__ a1d)
{
    __shared__ unsigned long long xs[128][33];     // x value duplicated into both f32x2 halves
    __shared__ __align__(16) float ws[32][64];
    const int t = threadIdx.x;
    const int rowblk = blockIdx.x * 128;
    const int tr = t >> 3;   // 0..15
    const int tc = t & 7;    // 0..7 (head)

    unsigned long long acc[8][4];
    #pragma unroll
    for (int r = 0; r < 8; r++)
        #pragma unroll
        for (int j = 0; j < 4; j++) acc[r][j] = 0ULL;

    for (int k0 = 0; k0 < 256; k0 += 32) {
        #pragma unroll
        for (int r = 0; r < 32; r++) {
            int row = (r << 2) + (t >> 5);
            int grow = rowblk + row;
            float v = (grow < NN) ? x[grow * 256 + k0 + (t & 31)] : 0.f;
            unsigned long long p;
            asm("mov.b64 %0, {%1, %1};" : "=l"(p) : "f"(v));
            xs[row][t & 31] = p;
        }
        #pragma unroll
        for (int r = 0; r < 16; r++) {
            int idx = (r << 7) + t;
            ws[idx >> 6][idx & 63] = W1[(k0 + (idx >> 6)) * 64 + (idx & 63)];
        }
        __syncthreads();
        #pragma unroll 8
        for (int k = 0; k < 32; k++) {
            const unsigned long long* bp = (const unsigned long long*)&ws[k][tc << 3];
            unsigned long long b0 = bp[0], b1 = bp[1], b2 = bp[2], b3 = bp[3];
            #pragma unroll
            for (int r = 0; r < 8; r++) {
                unsigned long long a2 = xs[tr + (r << 4)][k];
                asm("fma.rn.f32x2 %0, %4, %5, %0;\n\t"
                    "fma.rn.f32x2 %1, %4, %6, %1;\n\t"
                    "fma.rn.f32x2 %2, %4, %7, %2;\n\t"
                    "fma.rn.f32x2 %3, %4, %8, %3;"
                    : "+l"(acc[r][0]), "+l"(acc[r][1]), "+l"(acc[r][2]), "+l"(acc[r][3])
                    : "l"(a2), "l"(b0), "l"(b1), "l"(b2), "l"(b3));
            }
        }
        __syncthreads();
    }

    float av[8], bv[8];
    #pragma unroll
    for (int d = 0; d < 8; d++) { av[d] = a1s[(tc << 3) + d]; bv[d] = a1d[(tc << 3) + d]; }
    #pragma unroll
    for (int r = 0; r < 8; r++) {
        int grow = rowblk + tr + (r << 4);
        if (grow >= NN) continue;
        float s = 0.f, tt = 0.f;
        float2* hp = (float2*)&g_h1[grow * 64 + (tc << 3)];
        #pragma unroll
        for (int j = 0; j < 4; j++) {
            unsigned long long u = acc[r][j];
            float lo = __uint_as_float((unsigned)u);
            float hi = __uint_as_float((unsigned)(u >> 32));
            hp[j] = make_float2(lo, hi);
            s  += lo * av[2 * j] + hi * av[2 * j + 1];
            tt += lo * bv[2 * j] + hi * bv[2 * j + 1];
        }
        g_s1[grow * 8 + tc] = s;
        g_t1[grow * 8 + tc] = tt;
    }
}

// ---------------- Layer-1 aggregation: warp per dst node, online softmax, no atomics ----------------
__global__ void k_agg1() {
    int gw = (blockIdx.x * blockDim.x + threadIdx.x) >> 5;
    if (gw >= NN) return;
    const int n = gw;
    const int lane = threadIdx.x & 31;
    const int ha = lane >> 3;        // head for ch0 (0..3)
    const int hb = ha + 4;           // head for ch1
    const int ch0 = lane, ch1 = lane + 32;

    const float ta = g_t1[n * 8 + ha];
    const float tb = g_t1[n * 8 + hb];
    const int j0 = g_off[n], j1 = g_off[n + 1];

    float ma = -INFINITY, mb = -INFINITY;
    float da = 0.f, db = 0.f, A0 = 0.f, A1 = 0.f;

    for (int j = j0; j < j1; j++) {
        int src = __ldg(&g_srcs[j]);
        float ea = __ldg(&g_s1[src * 8 + ha]) + ta;
        float eb = __ldg(&g_s1[src * 8 + hb]) + tb;
        ea = ea > 0.f ? ea : 0.2f * ea;
        eb = eb > 0.f ? eb : 0.2f * eb;
        if (ea > ma) { float sc = __expf(ma - ea); da *= sc; A0 *= sc; ma = ea; }
        if (eb > mb) { float sc = __expf(mb - eb); db *= sc; A1 *= sc; mb = eb; }
        float pa = __expf(ea - ma);
        float pb = __expf(eb - mb);
        da += pa; db += pb;
        A0 += pa * __ldg(&g_h1[src * 64 + ch0]);
        A1 += pb * __ldg(&g_h1[src * 64 + ch1]);
    }
    float r0 = A0 / (da + 1e-16f);
    float r1 = A1 / (db + 1e-16f);
    g_z[n * 64 + ch0] = r0 > 0.f ? r0 : expm1f(r0);   // elu
    g_z[n * 64 + ch1] = r1 > 0.f ? r1 : expm1f(r1);
}

// ---------------- GEMM2: h2 = z @ W2 (+ s2/t2 epilogue) ----------------
__global__ __launch_bounds__(128) void k_gemm2(
    const float* __restrict__ W2, const float* __restrict__ a2s, const float* __restrict__ a2d)
{
    __shared__ float zs[128][65];                 // pad 65 -> conflict-free column reads
    __shared__ __align__(16) float w2s[1024];
    const int t = threadIdx.x;
    const int base = blockIdx.x * 128;

    #pragma unroll
    for (int r = 0; r < 64; r++) {
        int i = (r << 7) + t;
        int row = i >> 6, col = i & 63;
        int grow = base + row;
        zs[row][col] = (grow < NN) ? g_z[grow * 64 + col] : 0.f;
    }
    #pragma unroll
    for (int r = 0; r < 8; r++) w2s[(r << 7) + t] = W2[(r << 7) + t];
    __syncthreads();

    int row = base + t;
    if (row >= NN) return;

    float acc[16];
    #pragma unroll
    for (int c = 0; c < 16; c++) acc[c] = 0.f;

    #pragma unroll 8
    for (int k = 0; k < 64; k++) {
        float a = zs[t][k];
        const float4* wp = (const float4*)&w2s[k << 4];
        float4 w0 = wp[0], w1 = wp[1], w2 = wp[2], w3 = wp[3];
        acc[0]  += a * w0.x; acc[1]  += a * w0.y; acc[2]  += a * w0.z; acc[3]  += a * w0.w;
        acc[4]  += a * w1.x; acc[5]  += a * w1.y; acc[6]  += a * w1.z; acc[7]  += a * w1.w;
        acc[8]  += a * w2.x; acc[9]  += a * w2.y; acc[10] += a * w2.z; acc[11] += a * w2.w;
        acc[12] += a * w3.x; acc[13] += a * w3.y; acc[14] += a * w3.z; acc[15] += a * w3.w;
    }

    float s = 0.f, tt = 0.f;
    #pragma unroll
    for (int c = 0; c < 16; c++) { s += acc[c] * a2s[c]; tt += acc[c] * a2d[c]; }
    g_s2[row] = s;
    g_t2[row] = tt;

    float4* hp = (float4*)&g_h2[row * 16];
    hp[0] = make_float4(acc[0],  acc[1],  acc[2],  acc[3]);
    hp[1] = make_float4(acc[4],  acc[5],  acc[6],  acc[7]);
    hp[2] = make_float4(acc[8],  acc[9],  acc[10], acc[11]);
    hp[3] = make_float4(acc[12], acc[13], acc[14], acc[15]);
}

// ---------------- Layer-2 aggregation + log_softmax fused ----------------
__global__ void k_agg2(float* __restrict__ out) {
    int gw = (blockIdx.x * blockDim.x + threadIdx.x) >> 5;
    if (gw >= NN) return;
    const int n = gw;
    const int lane = threadIdx.x & 31;
    const int ch = lane & 15;

    const float tn = g_t2[n];
    const int j0 = g_off[n], j1 = g_off[n + 1];

    float m = -INFINITY, d = 0.f, A = 0.f;
    for (int j = j0; j < j1; j++) {
        int src = __ldg(&g_srcs[j]);
        float e = __ldg(&g_s2[src]) + tn;
        e = e > 0.f ? e : 0.2f * e;
        if (e > m) { float sc = __expf(m - e); d *= sc; A *= sc; m = e; }
        float p = __expf(e - m);
        d += p;
        A += p * __ldg(&g_h2[src * 16 + ch]);
    }
    float l = A / (d + 1e-16f);

    // log_softmax over the 16 class lanes (both 16-lane halves compute identically)
    float mx = l;
    #pragma unroll
    for (int o = 8; o; o >>= 1) mx = fmaxf(mx, __shfl_xor_sync(0xffffffffu, mx, o, 16));
    float ex = expf(l - mx);
    float sm = ex;
    #pragma unroll
    for (int o = 8; o; o >>= 1) sm += __shfl_xor_sync(0xffffffffu, sm, o, 16);
    float res = l - mx - logf(sm);
    if (lane < 16) out[n * 16 + ch] = res;
}

// ---------------- launch ----------------
extern "C" void kernel_launch(void* const* d_in, const int* in_sizes, int n_in,
                              void* d_out, int out_size) {
    const float* x   = (const float*)d_in[0];
    const int*   ei  = (const int*)  d_in[1];   // int32 or int64; detected on device
    const float* W1  = (const float*)d_in[2];
    const float* a1s = (const float*)d_in[3];
    const float* a1d = (const float*)d_in[4];
    const float* W2  = (const float*)d_in[5];
    const float* a2s = (const float*)d_in[6];
    const float* a2d = (const float*)d_in[7];
    float* out = (float*)d_out;

    k_detect  <<<1, 32>>>(ei);
    k_zero_deg<<<(NN + 255) / 256, 256>>>();
    k_hist    <<<(NE + 255) / 256, 256>>>(ei);
    k_scanA   <<<SCAN_B, 1024>>>();
    k_scanB   <<<1, 32>>>();
    k_scanC   <<<(NN + 255) / 256, 256>>>();
    k_scatter <<<(NE + 255) / 256, 256>>>(ei);

    k_gemm1   <<<(NN + 127) / 128, 128>>>(x, W1, a1s, a1d);
    k_agg1    <<<(NN * 32 + 255) / 256, 256>>>();
    k_gemm2   <<<(NN + 127) / 128, 128>>>(W2, a2s, a2d);
    k_agg2    <<<(NN * 32 + 255) / 256, 256>>>(out);
}

// round 2
// speedup vs baseline: 1.3933x; 1.3933x over previous
#include <cuda_runtime.h>
#include <math.h>

#define NN 100000
#define NE 1600000
#define SCAN_B 98   // ceil(NN/1024)

// ---------------- scratch (static device memory; no allocations) ----------------
__device__ int   g_is64;
__device__ int   g_deg[NN];
__device__ int   g_incl[NN];
__device__ int   g_bsum[SCAN_B];
__device__ int   g_boff[SCAN_B];
__device__ int   g_off[NN + 1];
__device__ int   g_cur[NN];
__device__ int   g_srcs[NE];
__device__ float g_h1[NN * 64];
__device__ float g_s1[NN * 8];
__device__ float g_t1[NN * 8];
__device__ float g_z [NN * 64];
__device__ float g_h2[NN * 16];
__device__ float g_s2[NN];
__device__ float g_t2[NN];

// ---------------- edge dtype detection (int64 vs int32) ----------------
__global__ void k_detect(const int* __restrict__ w) {
    if (threadIdx.x == 0) {
        int is64 = 1;
        #pragma unroll
        for (int k = 0; k < 8; k++)
            if (w[2 * k + 1] != 0) is64 = 0;
        g_is64 = is64;
    }
}

__global__ void k_zero_deg() {
    int i = blockIdx.x * blockDim.x + threadIdx.x;
    if (i < NN) { g_deg[i] = 0; g_cur[i] = 0; }
}

__global__ void k_hist(const int* __restrict__ w) {
    int i = blockIdx.x * blockDim.x + threadIdx.x;
    if (i >= NE) return;
    long long di = g_is64 ? 2LL * (NE + (long long)i) : (long long)(NE + i);
    atomicAdd(&g_deg[w[di]], 1);
}

__global__ void k_scanA() {
    __shared__ int sh[1024];
    int i = blockIdx.x * 1024 + threadIdx.x;
    int v = (i < NN) ? g_deg[i] : 0;
    sh[threadIdx.x] = v;
    __syncthreads();
    #pragma unroll
    for (int ofs = 1; ofs < 1024; ofs <<= 1) {
        int add = (threadIdx.x >= ofs) ? sh[threadIdx.x - ofs] : 0;
        __syncthreads();
        sh[threadIdx.x] += add;
        __syncthreads();
    }
    if (i < NN) g_incl[i] = sh[threadIdx.x];
    if (threadIdx.x == 1023) g_bsum[blockIdx.x] = sh[1023];
}

// parallel scan over the 98 block sums (was a single-thread 15us serial loop)
__global__ void k_scanB() {
    __shared__ int sh[128];
    int t = threadIdx.x;
    int v = (t < SCAN_B) ? g_bsum[t] : 0;
    sh[t] = v;
    __syncthreads();
    #pragma unroll
    for (int ofs = 1; ofs < 128; ofs <<= 1) {
        int add = (t >= ofs) ? sh[t - ofs] : 0;
        __syncthreads();
        sh[t] += add;
        __syncthreads();
    }
    if (t < SCAN_B) g_boff[t] = sh[t] - v;   // exclusive
    if (t == 0) g_off[0] = 0;
}

__global__ void k_scanC() {
    int i = blockIdx.x * blockDim.x + threadIdx.x;
    if (i < NN) g_off[i + 1] = g_incl[i] + g_boff[i >> 10];
}

__global__ void k_scatter(const int* __restrict__ w) {
    int i = blockIdx.x * blockDim.x + threadIdx.x;
    if (i >= NE) return;
    int is64 = g_is64;
    int s = w[is64 ? 2LL * i : (long long)i];
    int d = w[is64 ? 2LL * (NE + (long long)i) : (long long)(NE + i)];
    int pos = g_off[d] + atomicAdd(&g_cur[d], 1);
    g_srcs[pos] = s;
}

// ---------------- GEMM1: h1 = x @ W1 (+ s1/t1 epilogue), packed f32x2 FFMA ----------------
__global__ __launch_bounds__(128, 4) void k_gemm1(
    const float* __restrict__ x, const float* __restrict__ W1,
    const float* __restrict__ a1s, const float* __restrict__ a1d)
{
    __shared__ unsigned long long xs[128][33];
    __shared__ __align__(16) float ws[32][64];
    const int t = threadIdx.x;
    const int rowblk = blockIdx.x * 128;
    const int tr = t >> 3;   // 0..15
    const int tc = t & 7;    // 0..7 (head)

    unsigned long long acc[8][4];
    #pragma unroll
    for (int r = 0; r < 8; r++)
        #pragma unroll
        for (int j = 0; j < 4; j++) acc[r][j] = 0ULL;

    for (int k0 = 0; k0 < 256; k0 += 32) {
        #pragma unroll
        for (int r = 0; r < 32; r++) {
            int row = (r << 2) + (t >> 5);
            int grow = rowblk + row;
            float v = (grow < NN) ? x[grow * 256 + k0 + (t & 31)] : 0.f;
            unsigned long long p;
            asm("mov.b64 %0, {%1, %1};" : "=l"(p) : "f"(v));
            xs[row][t & 31] = p;
        }
        #pragma unroll
        for (int r = 0; r < 16; r++) {
            int idx = (r << 7) + t;
            ws[idx >> 6][idx & 63] = W1[(k0 + (idx >> 6)) * 64 + (idx & 63)];
        }
        __syncthreads();
        #pragma unroll 8
        for (int k = 0; k < 32; k++) {
            const unsigned long long* bp = (const unsigned long long*)&ws[k][tc << 3];
            unsigned long long b0 = bp[0], b1 = bp[1], b2 = bp[2], b3 = bp[3];
            #pragma unroll
            for (int r = 0; r < 8; r++) {
                unsigned long long a2 = xs[tr + (r << 4)][k];
                asm("fma.rn.f32x2 %0, %4, %5, %0;\n\t"
                    "fma.rn.f32x2 %1, %4, %6, %1;\n\t"
                    "fma.rn.f32x2 %2, %4, %7, %2;\n\t"
                    "fma.rn.f32x2 %3, %4, %8, %3;"
                    : "+l"(acc[r][0]), "+l"(acc[r][1]), "+l"(acc[r][2]), "+l"(acc[r][3])
                    : "l"(a2), "l"(b0), "l"(b1), "l"(b2), "l"(b3));
            }
        }
        __syncthreads();
    }

    float av[8], bv[8];
    #pragma unroll
    for (int d = 0; d < 8; d++) { av[d] = a1s[(tc << 3) + d]; bv[d] = a1d[(tc << 3) + d]; }
    #pragma unroll
    for (int r = 0; r < 8; r++) {
        int grow = rowblk + tr + (r << 4);
        if (grow >= NN) continue;
        float s = 0.f, tt = 0.f;
        float2* hp = (float2*)&g_h1[grow * 64 + (tc << 3)];
        #pragma unroll
        for (int j = 0; j < 4; j++) {
            unsigned long long u = acc[r][j];
            float lo = __uint_as_float((unsigned)u);
            float hi = __uint_as_float((unsigned)(u >> 32));
            hp[j] = make_float2(lo, hi);
            s  += lo * av[2 * j] + hi * av[2 * j + 1];
            tt += lo * bv[2 * j] + hi * bv[2 * j + 1];
        }
        g_s1[grow * 8 + tc] = s;
        g_t1[grow * 8 + tc] = tt;
    }
}

// ---------------- Layer-1 aggregation: warp per dst node ----------------
// Plain exp (no running max): logits are bounded (|e| << 80), so softmax
// without the shift is mathematically identical and the loop is straight-line.
// Lane l owns head h=l>>2 and dim pair (l&3)*2 -> one exp + one LDG.64 per edge.
__global__ void k_agg1() {
    int n = (blockIdx.x * blockDim.x + threadIdx.x) >> 5;
    if (n >= NN) return;
    const int lane = threadIdx.x & 31;
    const int h  = lane >> 2;                 // head 0..7
    const int ch = (h << 3) + ((lane & 3) << 1);  // first channel of the pair

    const float tn = g_t1[n * 8 + h];
    const int j0 = g_off[n], j1 = g_off[n + 1];

    float d = 0.f, Ax = 0.f, Ay = 0.f;
    #pragma unroll 4
    for (int j = j0; j < j1; j++) {
        int src = __ldg(&g_srcs[j]);
        float e = __ldg(&g_s1[src * 8 + h]) + tn;
        e = e > 0.f ? e : 0.2f * e;
        float p = __expf(e);
        float2 hv = *(const float2*)&g_h1[src * 64 + ch];
        d += p;
        Ax += p * hv.x;
        Ay += p * hv.y;
    }
    float inv = 1.f / (d + 1e-16f);
    float r0 = Ax * inv, r1 = Ay * inv;
    float2 zo;
    zo.x = r0 > 0.f ? r0 : expm1f(r0);   // elu
    zo.y = r1 > 0.f ? r1 : expm1f(r1);
    *(float2*)&g_z[n * 64 + ch] = zo;
}

// ---------------- GEMM2: h2 = z @ W2 (+ s2/t2 epilogue) ----------------
__global__ __launch_bounds__(128) void k_gemm2(
    const float* __restrict__ W2, const float* __restrict__ a2s, const float* __restrict__ a2d)
{
    __shared__ float zs[128][65];
    __shared__ __align__(16) float w2s[1024];
    const int t = threadIdx.x;
    const int base = blockIdx.x * 128;

    #pragma unroll
    for (int r = 0; r < 64; r++) {
        int i = (r << 7) + t;
        int row = i >> 6, col = i & 63;
        int grow = base + row;
        zs[row][col] = (grow < NN) ? g_z[grow * 64 + col] : 0.f;
    }
    #pragma unroll
    for (int r = 0; r < 8; r++) w2s[(r << 7) + t] = W2[(r << 7) + t];
    __syncthreads();

    int row = base + t;
    if (row >= NN) return;

    float acc[16];
    #pragma unroll
    for (int c = 0; c < 16; c++) acc[c] = 0.f;

    #pragma unroll 8
    for (int k = 0; k < 64; k++) {
        float a = zs[t][k];
        const float4* wp = (const float4*)&w2s[k << 4];
        float4 w0 = wp[0], w1 = wp[1], w2 = wp[2], w3 = wp[3];
        acc[0]  += a * w0.x; acc[1]  += a * w0.y; acc[2]  += a * w0.z; acc[3]  += a * w0.w;
        acc[4]  += a * w1.x; acc[5]  += a * w1.y; acc[6]  += a * w1.z; acc[7]  += a * w1.w;
        acc[8]  += a * w2.x; acc[9]  += a * w2.y; acc[10] += a * w2.z; acc[11] += a * w2.w;
        acc[12] += a * w3.x; acc[13] += a * w3.y; acc[14] += a * w3.z; acc[15] += a * w3.w;
    }

    float s = 0.f, tt = 0.f;
    #pragma unroll
    for (int c = 0; c < 16; c++) { s += acc[c] * a2s[c]; tt += acc[c] * a2d[c]; }
    g_s2[row] = s;
    g_t2[row] = tt;

    float4* hp = (float4*)&g_h2[row * 16];
    hp[0] = make_float4(acc[0],  acc[1],  acc[2],  acc[3]);
    hp[1] = make_float4(acc[4],  acc[5],  acc[6],  acc[7]);
    hp[2] = make_float4(acc[8],  acc[9],  acc[10], acc[11]);
    hp[3] = make_float4(acc[12], acc[13], acc[14], acc[15]);
}

// ---------------- Layer-2 aggregation + log_softmax fused ----------------
__global__ void k_agg2(float* __restrict__ out) {
    int n = (blockIdx.x * blockDim.x + threadIdx.x) >> 5;
    if (n >= NN) return;
    const int lane = threadIdx.x & 31;
    const int ch = lane & 15;

    const float tn = g_t2[n];
    const int j0 = g_off[n], j1 = g_off[n + 1];

    float d = 0.f, A = 0.f;
    #pragma unroll 4
    for (int j = j0; j < j1; j++) {
        int src = __ldg(&g_srcs[j]);
        float e = __ldg(&g_s2[src]) + tn;
        e = e > 0.f ? e : 0.2f * e;
        float p = __expf(e);
        d += p;
        A += p * __ldg(&g_h2[src * 16 + ch]);
    }
    float l = A / (d + 1e-16f);

    // log_softmax over the 16 class lanes (both 16-lane halves identical)
    float mx = l;
    #pragma unroll
    for (int o = 8; o; o >>= 1) mx = fmaxf(mx, __shfl_xor_sync(0xffffffffu, mx, o, 16));
    float ex = expf(l - mx);
    float sm = ex;
    #pragma unroll
    for (int o = 8; o; o >>= 1) sm += __shfl_xor_sync(0xffffffffu, sm, o, 16);
    float res = l - mx - logf(sm);
    if (lane < 16) out[n * 16 + ch] = res;
}

// ---------------- launch ----------------
extern "C" void kernel_launch(void* const* d_in, const int* in_sizes, int n_in,
                              void* d_out, int out_size) {
    const float* x   = (const float*)d_in[0];
    const int*   ei  = (const int*)  d_in[1];
    const float* W1  = (const float*)d_in[2];
    const float* a1s = (const float*)d_in[3];
    const float* a1d = (const float*)d_in[4];
    const float* W2  = (const float*)d_in[5];
    const float* a2s = (const float*)d_in[6];
    const float* a2d = (const float*)d_in[7];
    float* out = (float*)d_out;

    k_detect  <<<1, 32>>>(ei);
    k_zero_deg<<<(NN + 255) / 256, 256>>>();
    k_hist    <<<(NE + 255) / 256, 256>>>(ei);
    k_scanA   <<<SCAN_B, 1024>>>();
    k_scanB   <<<1, 128>>>();
    k_scanC   <<<(NN + 255) / 256, 256>>>();
    k_scatter <<<(NE + 255) / 256, 256>>>(ei);

    k_gemm1   <<<(NN + 127) / 128, 128>>>(x, W1, a1s, a1d);
    k_agg1    <<<(NN * 32 + 255) / 256, 256>>>();
    k_gemm2   <<<(NN + 127) / 128, 128>>>(W2, a2s, a2d);
    k_agg2    <<<(NN * 32 + 255) / 256, 256>>>(out);
}

// round 3
// speedup vs baseline: 1.5859x; 1.1383x over previous
#include <cuda_runtime.h>
#include <math.h>

#define NN 100000
#define NE 1600000
#define SCAN_B 98   // ceil(NN/1024)

// ---------------- scratch (static device memory; no allocations) ----------------
__device__ int   g_is64;
__device__ int   g_deg[NN];
__device__ int   g_incl[NN];
__device__ int   g_bsum[SCAN_B];
__device__ int   g_boff[SCAN_B];
__device__ int   g_off[NN + 1];
__device__ int   g_cur[NN];
__device__ int   g_srcs[NE];
__device__ float g_h1[NN * 64];
__device__ float g_s1[NN * 8];
__device__ float g_t1[NN * 8];
__device__ float g_z [NN * 64];
__device__ float g_h2[NN * 16];
__device__ float g_s2[NN];
__device__ float g_t2[NN];

// ---------------- init: zero counters + detect edge dtype (int64 vs int32) ----------------
__global__ void k_init(const int* __restrict__ w) {
    int i = blockIdx.x * blockDim.x + threadIdx.x;
    if (i < NN) { g_deg[i] = 0; g_cur[i] = 0; }
    if (i == 0) {
        int is64 = 1;
        #pragma unroll
        for (int k = 0; k < 8; k++)
            if (w[2 * k + 1] != 0) is64 = 0;
        g_is64 = is64;
    }
}

__global__ void k_hist(const int* __restrict__ w) {
    int i = blockIdx.x * blockDim.x + threadIdx.x;
    if (i >= NE) return;
    long long di = g_is64 ? 2LL * (NE + (long long)i) : (long long)(NE + i);
    atomicAdd(&g_deg[w[di]], 1);
}

__global__ void k_scanA() {
    __shared__ int sh[1024];
    int i = blockIdx.x * 1024 + threadIdx.x;
    int v = (i < NN) ? g_deg[i] : 0;
    sh[threadIdx.x] = v;
    __syncthreads();
    #pragma unroll
    for (int ofs = 1; ofs < 1024; ofs <<= 1) {
        int add = (threadIdx.x >= ofs) ? sh[threadIdx.x - ofs] : 0;
        __syncthreads();
        sh[threadIdx.x] += add;
        __syncthreads();
    }
    if (i < NN) g_incl[i] = sh[threadIdx.x];
    if (threadIdx.x == 1023) g_bsum[blockIdx.x] = sh[1023];
}

__global__ void k_scanB() {
    __shared__ int sh[128];
    int t = threadIdx.x;
    int v = (t < SCAN_B) ? g_bsum[t] : 0;
    sh[t] = v;
    __syncthreads();
    #pragma unroll
    for (int ofs = 1; ofs < 128; ofs <<= 1) {
        int add = (t >= ofs) ? sh[t - ofs] : 0;
        __syncthreads();
        sh[t] += add;
        __syncthreads();
    }
    if (t < SCAN_B) g_boff[t] = sh[t] - v;   // exclusive
    if (t == 0) g_off[0] = 0;
}

__global__ void k_scanC() {
    int i = blockIdx.x * blockDim.x + threadIdx.x;
    if (i < NN) g_off[i + 1] = g_incl[i] + g_boff[i >> 10];
}

__global__ void k_scatter(const int* __restrict__ w) {
    int i = blockIdx.x * blockDim.x + threadIdx.x;
    if (i >= NE) return;
    int is64 = g_is64;
    int s = w[is64 ? 2LL * i : (long long)i];
    int d = w[is64 ? 2LL * (NE + (long long)i) : (long long)(NE + i)];
    int pos = g_off[d] + atomicAdd(&g_cur[d], 1);
    g_srcs[pos] = s;
}

// ---------------- GEMM1: h1 = x @ W1 (+ s1/t1 epilogue), packed f32x2 FFMA ----------------
__global__ __launch_bounds__(128, 4) void k_gemm1(
    const float* __restrict__ x, const float* __restrict__ W1,
    const float* __restrict__ a1s, const float* __restrict__ a1d)
{
    __shared__ unsigned long long xs[128][33];
    __shared__ __align__(16) float ws[32][64];
    const int t = threadIdx.x;
    const int rowblk = blockIdx.x * 128;
    const int tr = t >> 3;   // 0..15
    const int tc = t & 7;    // 0..7 (head)

    unsigned long long acc[8][4];
    #pragma unroll
    for (int r = 0; r < 8; r++)
        #pragma unroll
        for (int j = 0; j < 4; j++) acc[r][j] = 0ULL;

    for (int k0 = 0; k0 < 256; k0 += 32) {
        #pragma unroll
        for (int r = 0; r < 32; r++) {
            int row = (r << 2) + (t >> 5);
            int grow = rowblk + row;
            float v = (grow < NN) ? x[grow * 256 + k0 + (t & 31)] : 0.f;
            unsigned long long p;
            asm("mov.b64 %0, {%1, %1};" : "=l"(p) : "f"(v));
            xs[row][t & 31] = p;
        }
        #pragma unroll
        for (int r = 0; r < 16; r++) {
            int idx = (r << 7) + t;
            ws[idx >> 6][idx & 63] = W1[(k0 + (idx >> 6)) * 64 + (idx & 63)];
        }
        __syncthreads();
        #pragma unroll 8
        for (int k = 0; k < 32; k++) {
            const unsigned long long* bp = (const unsigned long long*)&ws[k][tc << 3];
            unsigned long long b0 = bp[0], b1 = bp[1], b2 = bp[2], b3 = bp[3];
            #pragma unroll
            for (int r = 0; r < 8; r++) {
                unsigned long long a2 = xs[tr + (r << 4)][k];
                asm("fma.rn.f32x2 %0, %4, %5, %0;\n\t"
                    "fma.rn.f32x2 %1, %4, %6, %1;\n\t"
                    "fma.rn.f32x2 %2, %4, %7, %2;\n\t"
                    "fma.rn.f32x2 %3, %4, %8, %3;"
                    : "+l"(acc[r][0]), "+l"(acc[r][1]), "+l"(acc[r][2]), "+l"(acc[r][3])
                    : "l"(a2), "l"(b0), "l"(b1), "l"(b2), "l"(b3));
            }
        }
        __syncthreads();
    }

    float av[8], bv[8];
    #pragma unroll
    for (int d = 0; d < 8; d++) { av[d] = a1s[(tc << 3) + d]; bv[d] = a1d[(tc << 3) + d]; }
    #pragma unroll
    for (int r = 0; r < 8; r++) {
        int grow = rowblk + tr + (r << 4);
        if (grow >= NN) continue;
        float s = 0.f, tt = 0.f;
        float2* hp = (float2*)&g_h1[grow * 64 + (tc << 3)];
        #pragma unroll
        for (int j = 0; j < 4; j++) {
            unsigned long long u = acc[r][j];
            float lo = __uint_as_float((unsigned)u);
            float hi = __uint_as_float((unsigned)(u >> 32));
            hp[j] = make_float2(lo, hi);
            s  += lo * av[2 * j] + hi * av[2 * j + 1];
            tt += lo * bv[2 * j] + hi * bv[2 * j + 1];
        }
        g_s1[grow * 8 + tc] = s;
        g_t1[grow * 8 + tc] = tt;
    }
}

// ---------------- Layer-1 aggregation: warp per dst node ----------------
// Plain exp (no running max): logits bounded -> unshifted softmax identical.
__global__ void k_agg1() {
    int n = (blockIdx.x * blockDim.x + threadIdx.x) >> 5;
    if (n >= NN) return;
    const int lane = threadIdx.x & 31;
    const int h  = lane >> 2;                     // head 0..7
    const int ch = (h << 3) + ((lane & 3) << 1);  // first channel of the pair

    const float tn = g_t1[n * 8 + h];
    const int j0 = g_off[n], j1 = g_off[n + 1];

    float d = 0.f, Ax = 0.f, Ay = 0.f;
    #pragma unroll 4
    for (int j = j0; j < j1; j++) {
        int src = __ldg(&g_srcs[j]);
        float e = __ldg(&g_s1[src * 8 + h]) + tn;
        e = e > 0.f ? e : 0.2f * e;
        float p = __expf(e);
        float2 hv = *(const float2*)&g_h1[src * 64 + ch];
        d += p;
        Ax += p * hv.x;
        Ay += p * hv.y;
    }
    float inv = 1.f / (d + 1e-16f);
    float r0 = Ax * inv, r1 = Ay * inv;
    float2 zo;
    zo.x = r0 > 0.f ? r0 : expm1f(r0);   // elu
    zo.y = r1 > 0.f ? r1 : expm1f(r1);
    *(float2*)&g_z[n * 64 + ch] = zo;
}

// ---------------- GEMM2: h2 = z @ W2 (+ s2/t2 epilogue) ----------------
__global__ __launch_bounds__(128) void k_gemm2(
    const float* __restrict__ W2, const float* __restrict__ a2s, const float* __restrict__ a2d)
{
    __shared__ float zs[128][65];
    __shared__ __align__(16) float w2s[1024];
    const int t = threadIdx.x;
    const int base = blockIdx.x * 128;

    #pragma unroll
    for (int r = 0; r < 64; r++) {
        int i = (r << 7) + t;
        int row = i >> 6, col = i & 63;
        int grow = base + row;
        zs[row][col] = (grow < NN) ? g_z[grow * 64 + col] : 0.f;
    }
    #pragma unroll
    for (int r = 0; r < 8; r++) w2s[(r << 7) + t] = W2[(r << 7) + t];
    __syncthreads();

    int row = base + t;
    if (row >= NN) return;

    float acc[16];
    #pragma unroll
    for (int c = 0; c < 16; c++) acc[c] = 0.f;

    #pragma unroll 8
    for (int k = 0; k < 64; k++) {
        float a = zs[t][k];
        const float4* wp = (const float4*)&w2s[k << 4];
        float4 w0 = wp[0], w1 = wp[1], w2 = wp[2], w3 = wp[3];
        acc[0]  += a * w0.x; acc[1]  += a * w0.y; acc[2]  += a * w0.z; acc[3]  += a * w0.w;
        acc[4]  += a * w1.x; acc[5]  += a * w1.y; acc[6]  += a * w1.z; acc[7]  += a * w1.w;
        acc[8]  += a * w2.x; acc[9]  += a * w2.y; acc[10] += a * w2.z; acc[11] += a * w2.w;
        acc[12] += a * w3.x; acc[13] += a * w3.y; acc[14] += a * w3.z; acc[15] += a * w3.w;
    }

    float s = 0.f, tt = 0.f;
    #pragma unroll
    for (int c = 0; c < 16; c++) { s += acc[c] * a2s[c]; tt += acc[c] * a2d[c]; }
    g_s2[row] = s;
    g_t2[row] = tt;

    float4* hp = (float4*)&g_h2[row * 16];
    hp[0] = make_float4(acc[0],  acc[1],  acc[2],  acc[3]);
    hp[1] = make_float4(acc[4],  acc[5],  acc[6],  acc[7]);
    hp[2] = make_float4(acc[8],  acc[9],  acc[10], acc[11]);
    hp[3] = make_float4(acc[12], acc[13], acc[14], acc[15]);
}

// ---------------- Layer-2 aggregation + log_softmax fused ----------------
// Half-warp split: lanes 0-15 take even edges, 16-31 odd, combine via shfl.
__global__ void k_agg2(float* __restrict__ out) {
    int n = (blockIdx.x * blockDim.x + threadIdx.x) >> 5;
    if (n >= NN) return;
    const int lane = threadIdx.x & 31;
    const int ch = lane & 15;
    const int half = lane >> 4;        // 0 or 1

    const float tn = g_t2[n];
    const int j0 = g_off[n], j1 = g_off[n + 1];

    float d = 0.f, A = 0.f;
    #pragma unroll 2
    for (int j = j0 + half; j < j1; j += 2) {
        int src = __ldg(&g_srcs[j]);
        float e = __ldg(&g_s2[src]) + tn;
        e = e > 0.f ? e : 0.2f * e;
        float p = __expf(e);
        d += p;
        A += p * __ldg(&g_h2[src * 16 + ch]);
    }
    // combine the two half-warp partials (lane i pairs with lane i^16, same ch)
    d += __shfl_xor_sync(0xffffffffu, d, 16);
    A += __shfl_xor_sync(0xffffffffu, A, 16);

    float l = A / (d + 1e-16f);

    // log_softmax over the 16 class lanes (both halves identical)
    float mx = l;
    #pragma unroll
    for (int o = 8; o; o >>= 1) mx = fmaxf(mx, __shfl_xor_sync(0xffffffffu, mx, o, 16));
    float ex = expf(l - mx);
    float sm = ex;
    #pragma unroll
    for (int o = 8; o; o >>= 1) sm += __shfl_xor_sync(0xffffffffu, sm, o, 16);
    float res = l - mx - logf(sm);
    if (lane < 16) out[n * 16 + ch] = res;
}

// ---------------- launch: CSR build on a side stream, overlapped with GEMM1 ----------------
static cudaStream_t g_side = 0;
static cudaEvent_t  g_evFork = 0, g_evJoin = 0;
static int g_res_ok = -1;

extern "C" void kernel_launch(void* const* d_in, const int* in_sizes, int n_in,
                              void* d_out, int out_size) {
    const float* x   = (const float*)d_in[0];
    const int*   ei  = (const int*)  d_in[1];
    const float* W1  = (const float*)d_in[2];
    const float* a1s = (const float*)d_in[3];
    const float* a1d = (const float*)d_in[4];
    const float* W2  = (const float*)d_in[5];
    const float* a2s = (const float*)d_in[6];
    const float* a2d = (const float*)d_in[7];
    float* out = (float*)d_out;

    if (g_res_ok < 0) {   // one-time resource creation (first call is uncaptured)
        cudaError_t e1 = cudaStreamCreateWithFlags(&g_side, cudaStreamNonBlocking);
        cudaError_t e2 = cudaEventCreateWithFlags(&g_evFork, cudaEventDisableTiming);
        cudaError_t e3 = cudaEventCreateWithFlags(&g_evJoin, cudaEventDisableTiming);
        g_res_ok = (e1 == cudaSuccess && e2 == cudaSuccess && e3 == cudaSuccess) ? 1 : 0;
    }
    cudaStream_t cs = (g_res_ok == 1) ? g_side : 0;  // CSR stream (fallback: serial)

    if (g_res_ok == 1) {
        cudaEventRecord(g_evFork, 0);
        cudaStreamWaitEvent(g_side, g_evFork, 0);
    }

    // CSR build chain (independent of GEMM1)
    k_init    <<<(NN + 255) / 256, 256, 0, cs>>>(ei);
    k_hist    <<<(NE + 255) / 256, 256, 0, cs>>>(ei);
    k_scanA   <<<SCAN_B, 1024, 0, cs>>>();
    k_scanB   <<<1, 128, 0, cs>>>();
    k_scanC   <<<(NN + 255) / 256, 256, 0, cs>>>();
    k_scatter <<<(NE + 255) / 256, 256, 0, cs>>>(ei);

    // GEMM1 on the capture stream, concurrent with CSR build
    k_gemm1   <<<(NN + 127) / 128, 128>>>(x, W1, a1s, a1d);

    if (g_res_ok == 1) {
        cudaEventRecord(g_evJoin, g_side);
        cudaStreamWaitEvent(0, g_evJoin, 0);
    }

    k_agg1    <<<(NN * 32 + 255) / 256, 256>>>();
    k_gemm2   <<<(NN + 127) / 128, 128>>>(W2, a2s, a2d);
    k_agg2    <<<(NN * 32 + 255) / 256, 256>>>(out);
}